// round 4
// baseline (speedup 1.0000x reference)
#include <cuda_runtime.h>
#include <cstdint>

// Z gate (DIM=2, S=1) on wires {0,5,11} of a 24-qubit register.
// Harness output is N float32 = real part of the complex result:
//   out[n] = (-1)^popc(n & SIGN_MASK) * x_real[n]
// Wire i <-> bit (23 - i) of the flat index -> bits 23, 18, 12.
// x_imag is mathematically irrelevant to the float32-cast output; not read.

#define NELEM (1u << 24)
#define SIGN_MASK ((1u << 23) | (1u << 18) | (1u << 12))

__global__ void __launch_bounds__(256) z_phase_kernel(
    const float4* __restrict__ xr,
    float4* __restrict__ out,
    unsigned n_vec4)                 // number of float4 elements to process
{
    unsigned t = blockIdx.x * blockDim.x + threadIdx.x;
    if (t >= n_vec4) return;

    unsigned n0 = t << 2;
    // Sign bits (12,18,23) are constant across 4 consecutive elements.
    float s = (__popc(n0 & SIGN_MASK) & 1) ? -1.0f : 1.0f;

    float4 r = xr[t];
    r.x *= s; r.y *= s; r.z *= s; r.w *= s;
    out[t] = r;
}

extern "C" void kernel_launch(void* const* d_in, const int* in_sizes, int n_in,
                              void* d_out, int out_size)
{
    const float4* xr = (const float4*)d_in[0];
    float4* out = (float4*)d_out;

    // Writable/readable element count: min(input elems, out_size), in float4s.
    unsigned n = (unsigned)in_sizes[0];
    if ((unsigned)out_size < n) n = (unsigned)out_size;
    if (n > NELEM) n = NELEM;
    unsigned n_vec4 = n >> 2;               // N is a power of two; exact

    const unsigned threads = 256;
    unsigned blocks = (n_vec4 + threads - 1) / threads;

    z_phase_kernel<<<blocks, threads>>>(xr, out, n_vec4);
}